// round 1
// baseline (speedup 1.0000x reference)
#include <cuda_runtime.h>

#define BB 8192
#define NN 4096
#define NT 512
#define CC (NN / NT)   // 8 elements per thread

__device__ double g_partial[BB];
__device__ int g_is64;

// Distinguish int64 vs int32 labels at runtime.
// For int64 (little-endian, values in [0,4096)), every odd 32-bit word is 0.
// For int32 labels holding a permutation of [0,4096), 32 consecutive odd words
// cannot all be zero (values are distinct).
__global__ void detect_kernel(const unsigned int* __restrict__ labw) {
    if (threadIdx.x == 0) {
        int ok = 1;
#pragma unroll
        for (int i = 1; i < 64; i += 2)
            if (labw[i] != 0u) ok = 0;
        g_is64 = ok;
    }
}

__global__ __launch_bounds__(NT) void listmle_kernel(
    const float* __restrict__ outputs,
    const void* __restrict__ labels)
{
    __shared__ float srow[NN];      // the row of outputs (16 KB)
    __shared__ float sredA[16];     // max reduction
    __shared__ float sredB[16];     // sum reduction
    __shared__ float swtot[16];     // per-warp scan totals / log sums
    __shared__ float swoff[16];     // per-warp exclusive offsets

    const int row  = blockIdx.x;
    const int tid  = threadIdx.x;
    const int lane = tid & 31;
    const int wid  = tid >> 5;

    // ---- Load row to smem; fused row-max and row-sum(outputs) ----
    const float4* o4 = (const float4*)(outputs + (size_t)row * NN);
    float mx = -3.0e38f, osum = 0.f;
#pragma unroll
    for (int i = 0; i < NN / 4 / NT; ++i) {   // 2 iterations
        float4 v = o4[tid + i * NT];
        ((float4*)srow)[tid + i * NT] = v;
        mx = fmaxf(fmaxf(mx, fmaxf(v.x, v.y)), fmaxf(v.z, v.w));
        osum += (v.x + v.y) + (v.z + v.w);
    }
#pragma unroll
    for (int o = 16; o; o >>= 1) {
        mx   = fmaxf(mx, __shfl_xor_sync(0xffffffffu, mx, o));
        osum += __shfl_xor_sync(0xffffffffu, osum, o);
    }
    if (lane == 0) { sredA[wid] = mx; sredB[wid] = osum; }
    __syncthreads();
    if (tid < 32) {
        float m2 = (tid < 16) ? sredA[tid] : -3.0e38f;
        float s2 = (tid < 16) ? sredB[tid] : 0.f;
#pragma unroll
        for (int o = 8; o; o >>= 1) {
            m2 = fmaxf(m2, __shfl_xor_sync(0xffffffffu, m2, o));
            s2 += __shfl_xor_sync(0xffffffffu, s2, o);
        }
        if (tid == 0) { sredA[0] = m2; sredB[0] = s2; }
    }
    __syncthreads();
    const float rowmax  = sredA[0];
    const float rowosum = sredB[0];

    // ---- Gather labels (vectorized) and compute exp(x - rowmax) ----
    int idx[CC];
    const int base = tid * CC;
    if (g_is64) {
        const longlong2* lp =
            (const longlong2*)((const long long*)labels + (size_t)row * NN + base);
#pragma unroll
        for (int k = 0; k < CC / 2; ++k) {
            longlong2 v = lp[k];
            idx[2 * k]     = (int)v.x;
            idx[2 * k + 1] = (int)v.y;
        }
    } else {
        const int4* lp =
            (const int4*)((const int*)labels + (size_t)row * NN + base);
#pragma unroll
        for (int k = 0; k < CC / 4; ++k) {
            int4 v = lp[k];
            idx[4 * k]     = v.x;
            idx[4 * k + 1] = v.y;
            idx[4 * k + 2] = v.z;
            idx[4 * k + 3] = v.w;
        }
    }

    float e[CC];
    float lsum = 0.f;
#pragma unroll
    for (int k = 0; k < CC; ++k) {
        e[k] = __expf(srow[idx[k]] - rowmax);
        lsum += e[k];
    }

    // ---- Block-wide exclusive prefix sum of per-thread chunk sums ----
    float inc = lsum;
#pragma unroll
    for (int o = 1; o < 32; o <<= 1) {
        float v = __shfl_up_sync(0xffffffffu, inc, o);
        if (lane >= o) inc += v;
    }
    if (lane == 31) swtot[wid] = inc;
    __syncthreads();
    if (tid == 0) {
        float acc = 0.f;
#pragma unroll
        for (int w = 0; w < 16; ++w) { float t = swtot[w]; swoff[w] = acc; acc += t; }
    }
    __syncthreads();

    // ---- Second pass: running prefix -> scores ----
    float run = swoff[wid] + (inc - lsum);   // exclusive prefix for this thread
    float logsum = 0.f;
#pragma unroll
    for (int k = 0; k < CC; ++k) {
        run += e[k];
        logsum += __logf(run);
    }

    // ---- Reduce sum of logs over the block, emit per-row partial ----
#pragma unroll
    for (int o = 16; o; o >>= 1)
        logsum += __shfl_xor_sync(0xffffffffu, logsum, o);
    if (lane == 0) swtot[wid] = logsum;      // safe: all prior swtot reads done pre-sync
    __syncthreads();
    if (tid == 0) {
        float t = 0.f;
#pragma unroll
        for (int w = 0; w < 16; ++w) t += swtot[w];
        // sum(scores) = sum(log(prefix)) + N*rowmax ; subtract sum(outputs)
        g_partial[row] = (double)t + (double)rowmax * (double)NN - (double)rowosum;
    }
}

__global__ void finalize_kernel(float* __restrict__ out) {
    __shared__ double s[256];
    double a = 0.0;
    for (int i = threadIdx.x; i < BB; i += 256) a += g_partial[i];
    s[threadIdx.x] = a;
    __syncthreads();
    for (int o = 128; o; o >>= 1) {
        if (threadIdx.x < o) s[threadIdx.x] += s[threadIdx.x + o];
        __syncthreads();
    }
    if (threadIdx.x == 0)
        out[0] = (float)(s[0] / ((double)BB * (double)NN));
}

extern "C" void kernel_launch(void* const* d_in, const int* in_sizes, int n_in,
                              void* d_out, int out_size) {
    const float* outputs = (const float*)d_in[0];
    const void*  labels  = d_in[1];
    detect_kernel<<<1, 32>>>((const unsigned int*)labels);
    listmle_kernel<<<BB, NT>>>(outputs, labels);
    finalize_kernel<<<1, 256>>>((float*)d_out);
}

// round 2
// speedup vs baseline: 1.1290x; 1.1290x over previous
#include <cuda_runtime.h>

#define BB 8192
#define NN 4096
#define NT 512
#define CC (NN / NT)   // 8 elements per thread

__device__ double g_partial[BB];

__global__ __launch_bounds__(NT) void listmle_kernel(
    const float* __restrict__ outputs,
    const void* __restrict__ labels)
{
    __shared__ float srow[NN];      // the row of outputs (16 KB)
    __shared__ float sredA[16];     // max reduction
    __shared__ float sredB[16];     // sum reduction
    __shared__ float swtot[16];     // per-warp scan totals / log sums
    __shared__ float swoff[16];     // per-warp exclusive offsets

    const int row  = blockIdx.x;
    const int tid  = threadIdx.x;
    const int lane = tid & 31;
    const int wid  = tid >> 5;
    const int base = tid * CC;

    // ---- dtype detect: broadcast load of 2 odd words of row 0's labels ----
    // int64 labels (<4096): odd 32-bit words are 0. int32 permutation:
    // elements 1 and 3 are distinct, so both words can't be 0.
    const unsigned int* labw = (const unsigned int*)labels;
    const unsigned int w1 = __ldg(labw + 1);
    const unsigned int w3 = __ldg(labw + 3);

    // ---- issue row loads immediately (independent of detect) ----
    const float4* o4 = (const float4*)(outputs + (size_t)row * NN);
    float4 v0 = __ldcs(o4 + tid);
    float4 v1 = __ldcs(o4 + tid + NT);

    // ---- issue label loads as early as possible (block-uniform branch) ----
    int idx[CC];
    if ((w1 | w3) == 0u) {   // int64 path (expected)
        const longlong2* lp =
            (const longlong2*)((const long long*)labels + (size_t)row * NN + base);
#pragma unroll
        for (int k = 0; k < CC / 2; ++k) {
            longlong2 v = __ldcs(lp + k);
            idx[2 * k]     = (int)v.x;
            idx[2 * k + 1] = (int)v.y;
        }
    } else {                 // int32 path
        const int4* lp =
            (const int4*)((const int*)labels + (size_t)row * NN + base);
#pragma unroll
        for (int k = 0; k < CC / 4; ++k) {
            int4 v = __ldcs(lp + k);
            idx[4 * k]     = v.x;
            idx[4 * k + 1] = v.y;
            idx[4 * k + 2] = v.z;
            idx[4 * k + 3] = v.w;
        }
    }

    // ---- store row to smem; fused row-max and row-sum(outputs) ----
    ((float4*)srow)[tid]      = v0;
    ((float4*)srow)[tid + NT] = v1;
    float mx = fmaxf(fmaxf(fmaxf(v0.x, v0.y), fmaxf(v0.z, v0.w)),
                     fmaxf(fmaxf(v1.x, v1.y), fmaxf(v1.z, v1.w)));
    float osum = ((v0.x + v0.y) + (v0.z + v0.w)) +
                 ((v1.x + v1.y) + (v1.z + v1.w));
#pragma unroll
    for (int o = 16; o; o >>= 1) {
        mx   = fmaxf(mx, __shfl_xor_sync(0xffffffffu, mx, o));
        osum += __shfl_xor_sync(0xffffffffu, osum, o);
    }
    if (lane == 0) { sredA[wid] = mx; sredB[wid] = osum; }
    __syncthreads();
    if (tid < 32) {
        float m2 = (tid < 16) ? sredA[tid] : -3.0e38f;
        float s2 = (tid < 16) ? sredB[tid] : 0.f;
#pragma unroll
        for (int o = 8; o; o >>= 1) {
            m2 = fmaxf(m2, __shfl_xor_sync(0xffffffffu, m2, o));
            s2 += __shfl_xor_sync(0xffffffffu, s2, o);
        }
        if (tid == 0) { sredA[0] = m2; sredB[0] = s2; }
    }
    __syncthreads();
    const float rowmax  = sredA[0];
    const float rowosum = sredB[0];

    // ---- smem gather + exp(x - rowmax) ----
    float e[CC];
    float lsum = 0.f;
#pragma unroll
    for (int k = 0; k < CC; ++k) {
        e[k] = __expf(srow[idx[k]] - rowmax);
        lsum += e[k];
    }

    // ---- block-wide exclusive prefix sum of per-thread chunk sums ----
    float inc = lsum;
#pragma unroll
    for (int o = 1; o < 32; o <<= 1) {
        float v = __shfl_up_sync(0xffffffffu, inc, o);
        if (lane >= o) inc += v;
    }
    if (lane == 31) swtot[wid] = inc;
    __syncthreads();
    if (tid == 0) {
        float acc = 0.f;
#pragma unroll
        for (int w = 0; w < 16; ++w) { float t = swtot[w]; swoff[w] = acc; acc += t; }
    }
    __syncthreads();

    // ---- running prefix -> sum of log(prefix) ----
    float run = swoff[wid] + (inc - lsum);   // exclusive prefix for this thread
    float logsum = 0.f;
#pragma unroll
    for (int k = 0; k < CC; ++k) {
        run += e[k];
        logsum += __logf(run);
    }

    // ---- reduce sum of logs over block, emit per-row partial ----
#pragma unroll
    for (int o = 16; o; o >>= 1)
        logsum += __shfl_xor_sync(0xffffffffu, logsum, o);
    __syncthreads();                       // protect swtot reuse
    if (lane == 0) swtot[wid] = logsum;
    __syncthreads();
    if (tid == 0) {
        float t = 0.f;
#pragma unroll
        for (int w = 0; w < 16; ++w) t += swtot[w];
        // sum(scores) = sum(log(prefix)) + N*rowmax ; subtract sum(outputs)
        g_partial[row] = (double)t + (double)rowmax * (double)NN - (double)rowosum;
    }
}

__global__ void finalize_kernel(float* __restrict__ out) {
    __shared__ double s[256];
    double a = 0.0;
    for (int i = threadIdx.x; i < BB; i += 256) a += g_partial[i];
    s[threadIdx.x] = a;
    __syncthreads();
    for (int o = 128; o; o >>= 1) {
        if (threadIdx.x < o) s[threadIdx.x] += s[threadIdx.x + o];
        __syncthreads();
    }
    if (threadIdx.x == 0)
        out[0] = (float)(s[0] / ((double)BB * (double)NN));
}

extern "C" void kernel_launch(void* const* d_in, const int* in_sizes, int n_in,
                              void* d_out, int out_size) {
    const float* outputs = (const float*)d_in[0];
    const void*  labels  = d_in[1];
    listmle_kernel<<<BB, NT>>>(outputs, labels);
    finalize_kernel<<<1, 256>>>((float*)d_out);
}